// round 6
// baseline (speedup 1.0000x reference)
#include <cuda_runtime.h>
#include <cstdint>
#include <cstddef>

#define FULLMASK 0xffffffffu

#define B_   16
#define N_   8192
#define CIN  64
#define CTOT 67
#define M_   1024
#define KK   32
#define HID  64
#define OUTC 128
#define SPAT (M_*KK)
#define NBLK (SPAT/64)      // 512 conv tiles per batch
#define EPSV 1e-5f

typedef unsigned long long ull;

// ---------------- device scratch (static, no allocation) ----------------
__device__ int   g_knn[B_*M_*KK];                       // 2 MB
__device__ float g_x1[(size_t)B_*HID*SPAT];             // 134 MB
__device__ float g_p1[B_*HID*NBLK*2];                   // 4 MB  conv1 partial sum/sumsq
__device__ float g_p2[B_*OUTC*NBLK*2];                  // 8 MB  conv2 partial sum/sumsq
__device__ float g_mx2[(size_t)B_*M_*OUTC];             // 8 MB  per (b,m,c) max over k
__device__ float g_mn2[(size_t)B_*M_*OUTC];             // 8 MB  per (b,m,c) min over k
__device__ float g_cs1[B_*HID*2];
__device__ float g_cs2[B_*OUTC*2];
__device__ float g_centfb[B_*M_*3];

// ---------------- packed f32x2 helpers ----------------
__device__ __forceinline__ ull pack2(float lo, float hi) {
    ull r;
    asm("mov.b64 %0, {%1, %2};" : "=l"(r)
        : "r"(__float_as_uint(lo)), "r"(__float_as_uint(hi)));
    return r;
}
__device__ __forceinline__ void unpack2(ull v, float& lo, float& hi) {
    unsigned a, b;
    asm("mov.b64 {%0, %1}, %2;" : "=r"(a), "=r"(b) : "l"(v));
    lo = __uint_as_float(a); hi = __uint_as_float(b);
}
__device__ __forceinline__ ull add2(ull a, ull b) {
    ull r; asm("add.rn.f32x2 %0, %1, %2;" : "=l"(r) : "l"(a), "l"(b)); return r;
}
__device__ __forceinline__ ull mul2(ull a, ull b) {
    ull r; asm("mul.rn.f32x2 %0, %1, %2;" : "=l"(r) : "l"(a), "l"(b)); return r;
}
__device__ __forceinline__ ull fma2(ull a, ull b, ull c) {
    ull r; asm("fma.rn.f32x2 %0, %1, %2, %3;" : "=l"(r) : "l"(a), "l"(b), "l"(c)); return r;
}

// ---------------- reduction helpers ----------------
__device__ __forceinline__ unsigned redux_max_u32(unsigned v) {
    unsigned r;
    asm volatile("redux.sync.max.u32 %0, %1, 0xffffffff;" : "=r"(r) : "r"(v));
    return r;
}
__device__ __forceinline__ unsigned redux_min_u32(unsigned v) {
    unsigned r;
    asm volatile("redux.sync.min.u32 %0, %1, 0xffffffff;" : "=r"(r) : "r"(v));
    return r;
}
__device__ __forceinline__ int redux_max_s32(int v) {
    int r;
    asm volatile("redux.sync.max.s32 %0, %1, 0xffffffff;" : "=r"(r) : "r"(v));
    return r;
}

// monotonic total-order key for float (handles negatives from cancellation)
__device__ __forceinline__ unsigned f2key(float f) {
    unsigned u = __float_as_uint(f);
    unsigned mask = ((unsigned)((int)u >> 31)) | 0x80000000u;
    return u ^ mask;
}

__device__ __forceinline__ float2 blk_reduce2(float s, float s2) {
    const int lane = threadIdx.x & 31, w = threadIdx.x >> 5;
    #pragma unroll
    for (int o = 16; o; o >>= 1) {
        s  += __shfl_down_sync(FULLMASK, s,  o);
        s2 += __shfl_down_sync(FULLMASK, s2, o);
    }
    __shared__ float rs[8], rq[8];
    if (lane == 0) { rs[w] = s; rq[w] = s2; }
    __syncthreads();
    if (w == 0) {
        s  = (lane < 8) ? rs[lane] : 0.f;
        s2 = (lane < 8) ? rq[lane] : 0.f;
        #pragma unroll
        for (int o = 4; o; o >>= 1) {
            s  += __shfl_down_sync(FULLMASK, s,  o);
            s2 += __shfl_down_sync(FULLMASK, s2, o);
        }
    }
    return make_float2(s, s2);
}

// ---------------- K1: farthest point sampling (packed f32x2 core) ----------------
// 512 threads, 16 points/thread packed as 8 f32x2 pairs. Distance math uses
// add.rn/mul.rn.f32x2 (per-lane identical to scalar __fsub_rn/__fmul_rn/__fadd_rn;
// subtraction realized as add of exactly-negated centroid). min/max tracking on
// the alu pipe (FMNMX) overlaps packed fma work. argmax index recovered by a
// descending rescan -> lowest point index on ties (jnp.argmax semantics).
__global__ void __launch_bounds__(512, 1)
fps_kernel(const float* __restrict__ xyz, float* __restrict__ cent) {
    extern __shared__ float sm[];
    float* xs = sm; float* ys = sm + N_; float* zs = sm + 2 * N_;
    __shared__ unsigned swb[2][16];
    __shared__ unsigned swi[2][16];
    const int b = blockIdx.x, t = threadIdx.x, lane = t & 31, w = t >> 5;
    const float* base = xyz + (size_t)b * N_ * 3;
    for (int p = t; p < N_; p += 512) {
        xs[p] = base[3 * p]; ys[p] = base[3 * p + 1]; zs[p] = base[3 * p + 2];
    }
    __syncthreads();

    ull px2[8], py2[8], pz2[8];
    float dist[16];
    #pragma unroll
    for (int j = 0; j < 8; j++) {
        const int p0 = t + (2 * j) * 512, p1 = p0 + 512;
        px2[j] = pack2(xs[p0], xs[p1]);
        py2[j] = pack2(ys[p0], ys[p1]);
        pz2[j] = pack2(zs[p0], zs[p1]);
        dist[2 * j] = 1e10f; dist[2 * j + 1] = 1e10f;
    }
    float cx = xs[0], cy = ys[0], cz = zs[0];
    if (t == 0) {
        size_t o = (size_t)b * M_ * 3;
        cent[o] = cx; cent[o + 1] = cy; cent[o + 2] = cz;
    }

    for (int it = 1; it < M_; ++it) {
        const ull ncx = pack2(-cx, -cx);   // p + (-c) == p - c exactly (IEEE)
        const ull ncy = pack2(-cy, -cy);
        const ull ncz = pack2(-cz, -cz);
        float mv = -1.f;
        #pragma unroll
        for (int j = 0; j < 8; j++) {
            ull dx = add2(px2[j], ncx);
            ull dy = add2(py2[j], ncy);
            ull dz = add2(pz2[j], ncz);
            // ((dx*dx + dy*dy) + dz*dz), each op .rn — matches scalar reference order
            ull d = add2(add2(mul2(dx, dx), mul2(dy, dy)), mul2(dz, dz));
            float d0, d1; unpack2(d, d0, d1);
            float n0 = fminf(dist[2 * j], d0);
            float n1 = fminf(dist[2 * j + 1], d1);
            dist[2 * j] = n0; dist[2 * j + 1] = n1;
            mv = fmaxf(mv, fmaxf(n0, n1));
        }
        // rescan descending -> mi = smallest point index with dist == mv
        unsigned mi = 0;
        #pragma unroll
        for (int k = 15; k >= 0; k--)
            if (dist[k] == mv) mi = (unsigned)(t + k * 512);

        unsigned mb = __float_as_uint(mv);          // dist >= 0 -> bits monotonic
        unsigned wm = redux_max_u32(mb);
        unsigned wi = redux_min_u32((mb == wm) ? mi : 0xFFFFFFFFu);
        const int pb = it & 1;
        if (lane == 0) { swb[pb][w] = wm; swi[pb][w] = wi; }
        __syncthreads();
        unsigned vb = (lane < 16) ? swb[pb][lane] : 0u;
        unsigned vi = (lane < 16) ? swi[pb][lane] : 0xFFFFFFFFu;
        unsigned gm = redux_max_u32(vb);
        unsigned far = redux_min_u32((vb == gm) ? vi : 0xFFFFFFFFu);
        cx = xs[far]; cy = ys[far]; cz = zs[far];
        if (t == 0) {
            size_t o = ((size_t)b * M_ + it) * 3;
            cent[o] = cx; cent[o + 1] = cy; cent[o + 2] = cz;
        }
        // no second barrier: next iteration writes the OTHER parity buffer
    }
}

// ---------------- K2: kNN top-32 (warp per centroid) ----------------
// top_k keeps lowest indices among value ties -> evict HIGHEST index among tied max
__global__ void __launch_bounds__(256, 1)
knn_kernel(const float* __restrict__ xyz, const float* __restrict__ cent) {
    extern __shared__ float sm[];
    float* xs = sm; float* ys = sm + N_; float* zs = sm + 2 * N_; float* xn = sm + 3 * N_;
    const int b = blockIdx.x, cb = blockIdx.y;
    const int t = threadIdx.x, lane = t & 31, w = t >> 5;
    const float* base = xyz + (size_t)b * N_ * 3;
    for (int p = t; p < N_; p += 256) {
        float x = base[3 * p], y = base[3 * p + 1], z = base[3 * p + 2];
        xs[p] = x; ys[p] = y; zs[p] = z;
        xn[p] = x * x + y * y + z * z;
    }
    __syncthreads();

    const int m0 = cb * 64 + w * 8;
    for (int mi = m0; mi < m0 + 8; ++mi) {
        size_t co = ((size_t)b * M_ + mi) * 3;
        float cx = cent[co], cy = cent[co + 1], cz = cent[co + 2];
        float cn = cx * cx + cy * cy + cz * cz;

        unsigned valkey; int vidx;
        {
            int p = lane;
            float d = cn + xn[p] - 2.f * (cx * xs[p] + cy * ys[p] + cz * zs[p]);
            valkey = f2key(d);
            vidx = p;
        }
        unsigned thr = redux_max_u32(valkey);

        for (int c0 = 32; c0 < N_; c0 += 32) {
            int p = c0 + lane;
            float d = cn + xn[p] - 2.f * (cx * xs[p] + cy * ys[p] + cz * zs[p]);
            unsigned dk = f2key(d);
            unsigned pend = __ballot_sync(FULLMASK, dk < thr);
            while (pend) {
                int src = __ffs(pend) - 1;
                pend &= pend - 1;
                unsigned dkj = __shfl_sync(FULLMASK, dk, src);
                if (dkj < thr) {
                    int pj = c0 + src;
                    unsigned vmax = redux_max_u32(valkey);
                    int cand = (valkey == vmax) ? vidx : -1;
                    int victimidx = redux_max_s32(cand);
                    if (valkey == vmax && vidx == victimidx) { valkey = dkj; vidx = pj; }
                    thr = redux_max_u32(valkey);
                }
            }
        }
        g_knn[((size_t)b * M_ + mi) * KK + lane] = vidx;
    }
}

// ---------------- K3: gather + conv1 (FFMA2 core, dup'd weights) ----------------
// dynamic smem: Wsd[CTOT*64*2] (weights duplicated as (w,w) pairs), Xs[CTOT*68]
__global__ void __launch_bounds__(256, 2)
conv1_kernel(const float* __restrict__ xyz, const float* __restrict__ feat,
             const float* __restrict__ w1, const float* __restrict__ b1,
             const float* __restrict__ cent) {
    extern __shared__ float c1sm[];
    float* Wsd = c1sm;                       // CTOT*64*2
    float* Xs  = c1sm + CTOT * 64 * 2;       // CTOT*68
    const int b = blockIdx.y, bx = blockIdx.x, s0 = bx * 64, tid = threadIdx.x;

    for (int i = tid; i < CTOT * 64; i += 256) {
        int cin = i >> 6, c = i & 63;
        float v = w1[c * CTOT + cin];
        Wsd[i * 2] = v; Wsd[i * 2 + 1] = v;
    }
    {
        const int ps = tid >> 2, r = tid & 3;
        const int s = s0 + ps, m = s >> 5, kk = s & 31;
        const int idx = g_knn[((size_t)b * M_ + m) * KK + kk];
        const float* fp = feat + ((size_t)b * N_ + idx) * CIN + r * 16;
        #pragma unroll
        for (int q = 0; q < 4; q++) {
            float4 v = *(const float4*)(fp + q * 4);
            int row = 3 + r * 16 + q * 4;
            Xs[(row + 0) * 68 + ps] = v.x;
            Xs[(row + 1) * 68 + ps] = v.y;
            Xs[(row + 2) * 68 + ps] = v.z;
            Xs[(row + 3) * 68 + ps] = v.w;
        }
        if (r == 0) {
            const float* xp = xyz + ((size_t)b * N_ + idx) * 3;
            const float* cp = cent + ((size_t)b * M_ + m) * 3;
            Xs[0 * 68 + ps] = xp[0] - cp[0];
            Xs[1 * 68 + ps] = xp[1] - cp[1];
            Xs[2 * 68 + ps] = xp[2] - cp[2];
        }
    }
    __syncthreads();

    const int ty = tid >> 4, tx = tid & 15;
    ull acc2[4][2];
    #pragma unroll
    for (int i = 0; i < 4; i++) {
        float bb = b1[ty * 4 + i];
        ull bp = pack2(bb, bb);
        acc2[i][0] = bp; acc2[i][1] = bp;
    }
    #pragma unroll 4
    for (int cin = 0; cin < CTOT; cin++) {
        const ulonglong2* wd = (const ulonglong2*)&Wsd[(cin * 64 + ty * 4) * 2];
        ulonglong2 w01 = wd[0], w23 = wd[1];      // (a0,a0)(a1,a1) / (a2,a2)(a3,a3)
        const ulonglong2* xv = (const ulonglong2*)&Xs[cin * 68 + tx * 4];
        ull b01 = xv->x, b23 = xv->y;
        acc2[0][0] = fma2(w01.x, b01, acc2[0][0]); acc2[0][1] = fma2(w01.x, b23, acc2[0][1]);
        acc2[1][0] = fma2(w01.y, b01, acc2[1][0]); acc2[1][1] = fma2(w01.y, b23, acc2[1][1]);
        acc2[2][0] = fma2(w23.x, b01, acc2[2][0]); acc2[2][1] = fma2(w23.x, b23, acc2[2][1]);
        acc2[3][0] = fma2(w23.y, b01, acc2[3][0]); acc2[3][1] = fma2(w23.y, b23, acc2[3][1]);
    }
    float acc[4][4];
    #pragma unroll
    for (int i = 0; i < 4; i++) {
        unpack2(acc2[i][0], acc[i][0], acc[i][1]);
        unpack2(acc2[i][1], acc[i][2], acc[i][3]);
    }
    #pragma unroll
    for (int i = 0; i < 4; i++) {
        int c = ty * 4 + i;
        float4 v = make_float4(acc[i][0], acc[i][1], acc[i][2], acc[i][3]);
        *(float4*)&g_x1[((size_t)b * HID + c) * SPAT + s0 + tx * 4] = v;
        float s = (acc[i][0] + acc[i][1]) + (acc[i][2] + acc[i][3]);
        float q = (acc[i][0] * acc[i][0] + acc[i][1] * acc[i][1])
                + (acc[i][2] * acc[i][2] + acc[i][3] * acc[i][3]);
        #pragma unroll
        for (int o = 8; o; o >>= 1) {
            s += __shfl_down_sync(FULLMASK, s, o, 16);
            q += __shfl_down_sync(FULLMASK, q, o, 16);
        }
        if (tx == 0) {
            int pi = ((b * HID + c) * NBLK + bx) * 2;
            g_p1[pi] = s; g_p1[pi + 1] = q;
        }
    }
}

// ---------------- K4/K6: reduce stats partials ----------------
__global__ void __launch_bounds__(256)
stats1_kernel() {
    const int bid = blockIdx.x;                    // b*HID + c
    float s = 0.f, q = 0.f;
    for (int i = threadIdx.x; i < NBLK; i += 256) {
        s += g_p1[(bid * NBLK + i) * 2];
        q += g_p1[(bid * NBLK + i) * 2 + 1];
    }
    float2 r = blk_reduce2(s, q);
    if (threadIdx.x == 0) { g_cs1[bid * 2] = r.x; g_cs1[bid * 2 + 1] = r.y; }
}

__global__ void __launch_bounds__(256)
stats2_kernel() {
    const int bid = blockIdx.x;                    // b*OUTC + c
    float s = 0.f, q = 0.f;
    for (int i = threadIdx.x; i < NBLK; i += 256) {
        s += g_p2[(bid * NBLK + i) * 2];
        q += g_p2[(bid * NBLK + i) * 2 + 1];
    }
    float2 r = blk_reduce2(s, q);
    if (threadIdx.x == 0) { g_cs2[bid * 2] = r.x; g_cs2[bid * 2 + 1] = r.y; }
}

// ---------------- K5: GN1+ReLU on load + conv2 (FFMA2, dup'd weights) ----------------
// dynamic smem: Wsd[HID*OUTC*2], Hs[HID*68], sc[HID], sh[HID]
__global__ void __launch_bounds__(256)
conv2_kernel(const float* __restrict__ w2, const float* __restrict__ b2,
             const float* __restrict__ g1w, const float* __restrict__ g1b) {
    extern __shared__ float dsm[];
    float* Wsd = dsm;                          // HID*OUTC*2 = 16384
    float* Hs  = dsm + HID * OUTC * 2;         // 64*68
    float* sc  = Hs + HID * 68;                // 64
    float* sh  = sc + HID;                     // 64
    const int b = blockIdx.y, bx = blockIdx.x, s0 = bx * 64, tid = threadIdx.x;

    for (int i = tid; i < HID * OUTC; i += 256) {
        int cin = i >> 7, c = i & 127;
        float v = w2[c * HID + cin];
        Wsd[i * 2] = v; Wsd[i * 2 + 1] = v;
    }
    if (tid < HID) {
        int c = tid, g = c >> 1, cb = b * HID + g * 2;
        float sum = g_cs1[cb * 2]     + g_cs1[(cb + 1) * 2];
        float sq  = g_cs1[cb * 2 + 1] + g_cs1[(cb + 1) * 2 + 1];
        float inv = 1.0f / 65536.0f;
        float mu = sum * inv;
        float var = sq * inv - mu * mu;
        float a = rsqrtf(var + EPSV) * g1w[c];
        sc[c] = a;
        sh[c] = g1b[c] - mu * a;
    }
    __syncthreads();
    {
        const int c = tid >> 2, sseg = (tid & 3) * 16;
        const float* p = g_x1 + ((size_t)b * HID + c) * SPAT + s0 + sseg;
        float a = sc[c], o = sh[c];
        #pragma unroll
        for (int q = 0; q < 4; q++) {
            float4 v = *(const float4*)(p + q * 4);
            Hs[c * 68 + sseg + q * 4 + 0] = fmaxf(fmaf(v.x, a, o), 0.f);
            Hs[c * 68 + sseg + q * 4 + 1] = fmaxf(fmaf(v.y, a, o), 0.f);
            Hs[c * 68 + sseg + q * 4 + 2] = fmaxf(fmaf(v.z, a, o), 0.f);
            Hs[c * 68 + sseg + q * 4 + 3] = fmaxf(fmaf(v.w, a, o), 0.f);
        }
    }
    __syncthreads();

    const int ty = tid >> 4, tx = tid & 15, c0 = ty * 8;
    ull acc2[8][2];
    #pragma unroll
    for (int i = 0; i < 8; i++) {
        float bb = b2[c0 + i];
        ull bp = pack2(bb, bb);
        acc2[i][0] = bp; acc2[i][1] = bp;
    }
    #pragma unroll 4
    for (int cin = 0; cin < HID; cin++) {
        const ulonglong2* wd = (const ulonglong2*)&Wsd[(cin * OUTC + c0) * 2];
        ulonglong2 wA = wd[0], wB = wd[1], wC = wd[2], wD = wd[3];
        const ulonglong2* xv = (const ulonglong2*)&Hs[cin * 68 + tx * 4];
        ull b01 = xv->x, b23 = xv->y;
        acc2[0][0] = fma2(wA.x, b01, acc2[0][0]); acc2[0][1] = fma2(wA.x, b23, acc2[0][1]);
        acc2[1][0] = fma2(wA.y, b01, acc2[1][0]); acc2[1][1] = fma2(wA.y, b23, acc2[1][1]);
        acc2[2][0] = fma2(wB.x, b01, acc2[2][0]); acc2[2][1] = fma2(wB.x, b23, acc2[2][1]);
        acc2[3][0] = fma2(wB.y, b01, acc2[3][0]); acc2[3][1] = fma2(wB.y, b23, acc2[3][1]);
        acc2[4][0] = fma2(wC.x, b01, acc2[4][0]); acc2[4][1] = fma2(wC.x, b23, acc2[4][1]);
        acc2[5][0] = fma2(wC.y, b01, acc2[5][0]); acc2[5][1] = fma2(wC.y, b23, acc2[5][1]);
        acc2[6][0] = fma2(wD.x, b01, acc2[6][0]); acc2[6][1] = fma2(wD.x, b23, acc2[6][1]);
        acc2[7][0] = fma2(wD.y, b01, acc2[7][0]); acc2[7][1] = fma2(wD.y, b23, acc2[7][1]);
    }
    float acc[8][4];
    #pragma unroll
    for (int i = 0; i < 8; i++) {
        unpack2(acc2[i][0], acc[i][0], acc[i][1]);
        unpack2(acc2[i][1], acc[i][2], acc[i][3]);
    }

    // epilogue: per-(c, m) max/min over k (width-8: tx 0-7 = m0, tx 8-15 = m1)
    // + per-channel sum/sumsq partials over the 64-spatial tile (width-16).
    const int m = (s0 >> 5) + (tx >> 3);
    #pragma unroll
    for (int i = 0; i < 8; i++) {
        const int c = c0 + i;
        float mx = fmaxf(fmaxf(acc[i][0], acc[i][1]), fmaxf(acc[i][2], acc[i][3]));
        float mn = fminf(fminf(acc[i][0], acc[i][1]), fminf(acc[i][2], acc[i][3]));
        #pragma unroll
        for (int o = 4; o; o >>= 1) {
            mx = fmaxf(mx, __shfl_down_sync(FULLMASK, mx, o, 8));
            mn = fminf(mn, __shfl_down_sync(FULLMASK, mn, o, 8));
        }
        if ((tx & 7) == 0) {
            g_mx2[((size_t)b * M_ + m) * OUTC + c] = mx;
            g_mn2[((size_t)b * M_ + m) * OUTC + c] = mn;
        }
        float s = (acc[i][0] + acc[i][1]) + (acc[i][2] + acc[i][3]);
        float q = (acc[i][0] * acc[i][0] + acc[i][1] * acc[i][1])
                + (acc[i][2] * acc[i][2] + acc[i][3] * acc[i][3]);
        #pragma unroll
        for (int o = 8; o; o >>= 1) {
            s += __shfl_down_sync(FULLMASK, s, o, 16);
            q += __shfl_down_sync(FULLMASK, q, o, 16);
        }
        if (tx == 0) {
            int pi = ((b * OUTC + c) * NBLK + bx) * 2;
            g_p2[pi] = s; g_p2[pi + 1] = q;
        }
    }
}

// ---------------- K7: GN2 affine on max/min (monotone -> exact) ----------------
__global__ void __launch_bounds__(256)
final_kernel(const float* __restrict__ g2w, const float* __restrict__ g2b,
             float* __restrict__ out) {
    const int b = blockIdx.y;
    const int tid = threadIdx.x;
    const int c = tid & 127;
    const int m = blockIdx.x * 2 + (tid >> 7);
    const int g = c >> 2, cb = b * OUTC + g * 4;
    float sum = 0.f, sq = 0.f;
    #pragma unroll
    for (int q = 0; q < 4; q++) {
        sum += g_cs2[(cb + q) * 2];
        sq  += g_cs2[(cb + q) * 2 + 1];
    }
    const float inv = 1.0f / 131072.0f;
    float mu = sum * inv;
    float var = sq * inv - mu * mu;
    float a = rsqrtf(var + EPSV) * g2w[c];
    float o = g2b[c] - mu * a;
    size_t off = ((size_t)b * M_ + m) * OUTC + c;
    float mx = g_mx2[off], mn = g_mn2[off];
    float v = (a >= 0.f) ? fmaf(mx, a, o) : fmaf(mn, a, o);
    out[off] = fmaxf(v, 0.f);
}

// ---------------- launch ----------------
extern "C" void kernel_launch(void* const* d_in, const int* in_sizes, int n_in,
                              void* d_out, int out_size) {
    const float* xyz  = (const float*)d_in[0];
    const float* feat = (const float*)d_in[1];
    const float* w1   = (const float*)d_in[2];
    const float* b1   = (const float*)d_in[3];
    const float* g1w  = (const float*)d_in[4];
    const float* g1b  = (const float*)d_in[5];
    const float* w2   = (const float*)d_in[6];
    const float* b2   = (const float*)d_in[7];
    const float* g2w  = (const float*)d_in[8];
    const float* g2b  = (const float*)d_in[9];

    float* out = (float*)d_out;
    float* cent;
    float* nf;
    if (out_size == B_ * M_ * 3 + B_ * M_ * OUTC) {
        cent = out;
        nf = out + (size_t)B_ * M_ * 3;
    } else {
        void* p = nullptr;
        cudaGetSymbolAddress(&p, g_centfb);
        cent = (float*)p;
        nf = out;
    }

    const int c1smem = (CTOT * 64 * 2 + CTOT * 68) * 4;
    const int c2smem = (HID * OUTC * 2 + HID * 68 + 2 * HID) * 4;
    cudaFuncSetAttribute(fps_kernel,  cudaFuncAttributeMaxDynamicSharedMemorySize, 3 * N_ * 4);
    cudaFuncSetAttribute(knn_kernel,  cudaFuncAttributeMaxDynamicSharedMemorySize, 4 * N_ * 4);
    cudaFuncSetAttribute(conv1_kernel, cudaFuncAttributeMaxDynamicSharedMemorySize, c1smem);
    cudaFuncSetAttribute(conv2_kernel, cudaFuncAttributeMaxDynamicSharedMemorySize, c2smem);

    fps_kernel<<<B_, 512, 3 * N_ * 4>>>(xyz, cent);
    knn_kernel<<<dim3(B_, 16), 256, 4 * N_ * 4>>>(xyz, cent);
    conv1_kernel<<<dim3(NBLK, B_), 256, c1smem>>>(xyz, feat, w1, b1, cent);
    stats1_kernel<<<B_ * HID, 256>>>();
    conv2_kernel<<<dim3(NBLK, B_), 256, c2smem>>>(w2, b2, g1w, g1b);
    stats2_kernel<<<B_ * OUTC, 256>>>();
    final_kernel<<<dim3(M_ / 2, B_), 256>>>(g2w, g2b, nf);
}

// round 7
// speedup vs baseline: 1.0854x; 1.0854x over previous
#include <cuda_runtime.h>
#include <cstdint>
#include <cstddef>

#define FULLMASK 0xffffffffu

#define B_   16
#define N_   8192
#define CIN  64
#define CTOT 67
#define M_   1024
#define KK   32
#define HID  64
#define OUTC 128
#define SPAT (M_*KK)
#define NBLK (SPAT/64)      // 512 conv2 tiles per batch
#define NB1  (SPAT/128)     // 256 conv1 tiles per batch
#define EPSV 1e-5f

typedef unsigned long long ull;

// ---------------- device scratch (static, no allocation) ----------------
__device__ int   g_knn[B_*M_*KK];                       // 2 MB
__device__ float g_x1[(size_t)B_*HID*SPAT];             // 134 MB
__device__ float g_p1[B_*HID*NB1*2];                    // 2 MB  conv1 partial sum/sumsq
__device__ float g_p2[B_*OUTC*NBLK*2];                  // 8 MB  conv2 partial sum/sumsq
__device__ float g_mx2[(size_t)B_*M_*OUTC];             // 8 MB  per (b,m,c) max over k
__device__ float g_mn2[(size_t)B_*M_*OUTC];             // 8 MB  per (b,m,c) min over k
__device__ float g_cs1[B_*HID*2];
__device__ float g_cs2[B_*OUTC*2];
__device__ float g_centfb[B_*M_*3];
__device__ int   g_dummy;

// ---------------- packed f32x2 helpers ----------------
__device__ __forceinline__ ull pack2(float lo, float hi) {
    ull r;
    asm("mov.b64 %0, {%1, %2};" : "=l"(r)
        : "r"(__float_as_uint(lo)), "r"(__float_as_uint(hi)));
    return r;
}
__device__ __forceinline__ void unpack2(ull v, float& lo, float& hi) {
    unsigned a, b;
    asm("mov.b64 {%0, %1}, %2;" : "=r"(a), "=r"(b) : "l"(v));
    lo = __uint_as_float(a); hi = __uint_as_float(b);
}
__device__ __forceinline__ ull add2(ull a, ull b) {
    ull r; asm("add.rn.f32x2 %0, %1, %2;" : "=l"(r) : "l"(a), "l"(b)); return r;
}
__device__ __forceinline__ ull mul2(ull a, ull b) {
    ull r; asm("mul.rn.f32x2 %0, %1, %2;" : "=l"(r) : "l"(a), "l"(b)); return r;
}
__device__ __forceinline__ ull fma2(ull a, ull b, ull c) {
    ull r; asm("fma.rn.f32x2 %0, %1, %2, %3;" : "=l"(r) : "l"(a), "l"(b), "l"(c)); return r;
}

// ---------------- reduction helpers ----------------
__device__ __forceinline__ unsigned redux_max_u32(unsigned v) {
    unsigned r;
    asm volatile("redux.sync.max.u32 %0, %1, 0xffffffff;" : "=r"(r) : "r"(v));
    return r;
}
__device__ __forceinline__ unsigned redux_min_u32(unsigned v) {
    unsigned r;
    asm volatile("redux.sync.min.u32 %0, %1, 0xffffffff;" : "=r"(r) : "r"(v));
    return r;
}
__device__ __forceinline__ int redux_max_s32(int v) {
    int r;
    asm volatile("redux.sync.max.s32 %0, %1, 0xffffffff;" : "=r"(r) : "r"(v));
    return r;
}

__device__ __forceinline__ unsigned f2key(float f) {
    unsigned u = __float_as_uint(f);
    unsigned mask = ((unsigned)((int)u >> 31)) | 0x80000000u;
    return u ^ mask;
}

__device__ __forceinline__ float2 blk_reduce2(float s, float s2) {
    const int lane = threadIdx.x & 31, w = threadIdx.x >> 5;
    #pragma unroll
    for (int o = 16; o; o >>= 1) {
        s  += __shfl_down_sync(FULLMASK, s,  o);
        s2 += __shfl_down_sync(FULLMASK, s2, o);
    }
    __shared__ float rs[8], rq[8];
    if (lane == 0) { rs[w] = s; rq[w] = s2; }
    __syncthreads();
    if (w == 0) {
        s  = (lane < 8) ? rs[lane] : 0.f;
        s2 = (lane < 8) ? rq[lane] : 0.f;
        #pragma unroll
        for (int o = 4; o; o >>= 1) {
            s  += __shfl_down_sync(FULLMASK, s,  o);
            s2 += __shfl_down_sync(FULLMASK, s2, o);
        }
    }
    return make_float2(s, s2);
}

// ---------------- K0: dummy (shifts ncu capture slot onto fps_kernel) --------
__global__ void dummy_kernel(int t) { if (threadIdx.x == 0) g_dummy = t; }

// ---------------- K1: farthest point sampling (packed f32x2 core) ------------
__global__ void __launch_bounds__(512, 1)
fps_kernel(const float* __restrict__ xyz, float* __restrict__ cent) {
    extern __shared__ float sm[];
    float* xs = sm; float* ys = sm + N_; float* zs = sm + 2 * N_;
    __shared__ unsigned swb[2][16];
    __shared__ unsigned swi[2][16];
    const int b = blockIdx.x, t = threadIdx.x, lane = t & 31, w = t >> 5;
    const float* base = xyz + (size_t)b * N_ * 3;
    for (int p = t; p < N_; p += 512) {
        xs[p] = base[3 * p]; ys[p] = base[3 * p + 1]; zs[p] = base[3 * p + 2];
    }
    __syncthreads();

    ull px2[8], py2[8], pz2[8];
    float dist[16];
    #pragma unroll
    for (int j = 0; j < 8; j++) {
        const int p0 = t + (2 * j) * 512, p1 = p0 + 512;
        px2[j] = pack2(xs[p0], xs[p1]);
        py2[j] = pack2(ys[p0], ys[p1]);
        pz2[j] = pack2(zs[p0], zs[p1]);
        dist[2 * j] = 1e10f; dist[2 * j + 1] = 1e10f;
    }
    float cx = xs[0], cy = ys[0], cz = zs[0];
    if (t == 0) {
        size_t o = (size_t)b * M_ * 3;
        cent[o] = cx; cent[o + 1] = cy; cent[o + 2] = cz;
    }

    for (int it = 1; it < M_; ++it) {
        const ull ncx = pack2(-cx, -cx);   // p + (-c) == p - c exactly (IEEE)
        const ull ncy = pack2(-cy, -cy);
        const ull ncz = pack2(-cz, -cz);
        float mv = -1.f;
        #pragma unroll
        for (int j = 0; j < 8; j++) {
            ull dx = add2(px2[j], ncx);
            ull dy = add2(py2[j], ncy);
            ull dz = add2(pz2[j], ncz);
            ull d = add2(add2(mul2(dx, dx), mul2(dy, dy)), mul2(dz, dz));
            float d0, d1; unpack2(d, d0, d1);
            float n0 = fminf(dist[2 * j], d0);
            float n1 = fminf(dist[2 * j + 1], d1);
            dist[2 * j] = n0; dist[2 * j + 1] = n1;
            mv = fmaxf(mv, fmaxf(n0, n1));
        }
        unsigned mi = 0;
        #pragma unroll
        for (int k = 15; k >= 0; k--)
            if (dist[k] == mv) mi = (unsigned)(t + k * 512);

        unsigned mb = __float_as_uint(mv);
        unsigned wm = redux_max_u32(mb);
        unsigned wi = redux_min_u32((mb == wm) ? mi : 0xFFFFFFFFu);
        const int pb = it & 1;
        if (lane == 0) { swb[pb][w] = wm; swi[pb][w] = wi; }
        __syncthreads();
        unsigned vb = (lane < 16) ? swb[pb][lane] : 0u;
        unsigned vi = (lane < 16) ? swi[pb][lane] : 0xFFFFFFFFu;
        unsigned gm = redux_max_u32(vb);
        unsigned far = redux_min_u32((vb == gm) ? vi : 0xFFFFFFFFu);
        cx = xs[far]; cy = ys[far]; cz = zs[far];
        if (t == 0) {
            size_t o = ((size_t)b * M_ + it) * 3;
            cent[o] = cx; cent[o + 1] = cy; cent[o + 2] = cz;
        }
    }
}

// ---------------- K2: kNN top-32 (warp per centroid) ----------------
__global__ void __launch_bounds__(256, 1)
knn_kernel(const float* __restrict__ xyz, const float* __restrict__ cent) {
    extern __shared__ float sm[];
    float* xs = sm; float* ys = sm + N_; float* zs = sm + 2 * N_; float* xn = sm + 3 * N_;
    const int b = blockIdx.x, cb = blockIdx.y;
    const int t = threadIdx.x, lane = t & 31, w = t >> 5;
    const float* base = xyz + (size_t)b * N_ * 3;
    for (int p = t; p < N_; p += 256) {
        float x = base[3 * p], y = base[3 * p + 1], z = base[3 * p + 2];
        xs[p] = x; ys[p] = y; zs[p] = z;
        xn[p] = x * x + y * y + z * z;
    }
    __syncthreads();

    const int m0 = cb * 64 + w * 8;
    for (int mi = m0; mi < m0 + 8; ++mi) {
        size_t co = ((size_t)b * M_ + mi) * 3;
        float cx = cent[co], cy = cent[co + 1], cz = cent[co + 2];
        float cn = cx * cx + cy * cy + cz * cz;

        unsigned valkey; int vidx;
        {
            int p = lane;
            float d = cn + xn[p] - 2.f * (cx * xs[p] + cy * ys[p] + cz * zs[p]);
            valkey = f2key(d);
            vidx = p;
        }
        unsigned thr = redux_max_u32(valkey);

        for (int c0 = 32; c0 < N_; c0 += 32) {
            int p = c0 + lane;
            float d = cn + xn[p] - 2.f * (cx * xs[p] + cy * ys[p] + cz * zs[p]);
            unsigned dk = f2key(d);
            unsigned pend = __ballot_sync(FULLMASK, dk < thr);
            while (pend) {
                int src = __ffs(pend) - 1;
                pend &= pend - 1;
                unsigned dkj = __shfl_sync(FULLMASK, dk, src);
                if (dkj < thr) {
                    int pj = c0 + src;
                    unsigned vmax = redux_max_u32(valkey);
                    int cand = (valkey == vmax) ? vidx : -1;
                    int victimidx = redux_max_s32(cand);
                    if (valkey == vmax && vidx == victimidx) { valkey = dkj; vidx = pj; }
                    thr = redux_max_u32(valkey);
                }
            }
        }
        g_knn[((size_t)b * M_ + mi) * KK + lane] = vidx;
    }
}

// ---------------- K3: gather + conv1 (8x8 reg-blocked FFMA2) ----------------
// 128 threads; block tile 64 cout x 128 spat. Thread: ty=tid&7, tx=tid>>3,
// covers couts {2ty+16p, +1} p=0..3 (packed pairs) x spat [tx*8, tx*8+8).
// Per cin per thread: 4 LDS.64 (W pairs) + 2 LDS.128 (X) + 8 mov64 + 32 FFMA2.
__global__ void __launch_bounds__(128)
conv1_kernel(const float* __restrict__ xyz, const float* __restrict__ feat,
             const float* __restrict__ w1, const float* __restrict__ b1,
             const float* __restrict__ cent) {
    extern __shared__ float c1sm[];
    float* Ws = c1sm;                        // [cin][64]
    float* Xs = c1sm + CTOT * 64;            // [cin][136]
    __shared__ ull spart_s[4][32];
    __shared__ ull spart_q[4][32];
    const int b = blockIdx.y, bx = blockIdx.x, s0 = bx * 128, tid = threadIdx.x;
    const int warp = tid >> 5, lane = tid & 31;

    for (int i = tid; i < CTOT * 64; i += 128) {
        int cin = i >> 6, c = i & 63;
        Ws[i] = w1[c * CTOT + cin];
    }
    {   // gather: one thread per spatial position, full 67-channel column
        const int ps = tid, s = s0 + ps, m = s >> 5, kk = s & 31;
        const int idx = g_knn[((size_t)b * M_ + m) * KK + kk];
        const float* fp = feat + ((size_t)b * N_ + idx) * CIN;
        #pragma unroll
        for (int q = 0; q < 16; q++) {
            float4 v = *(const float4*)(fp + q * 4);
            int row = 3 + q * 4;
            Xs[(row + 0) * 136 + ps] = v.x;
            Xs[(row + 1) * 136 + ps] = v.y;
            Xs[(row + 2) * 136 + ps] = v.z;
            Xs[(row + 3) * 136 + ps] = v.w;
        }
        const float* xp = xyz + ((size_t)b * N_ + idx) * 3;
        const float* cp = cent + ((size_t)b * M_ + m) * 3;
        Xs[0 * 136 + ps] = xp[0] - cp[0];
        Xs[1 * 136 + ps] = xp[1] - cp[1];
        Xs[2 * 136 + ps] = xp[2] - cp[2];
    }
    __syncthreads();

    const int ty = tid & 7, tx = tid >> 3, sbase = tx * 8;
    ull acc[4][8];
    #pragma unroll
    for (int p = 0; p < 4; p++) {
        int c = 2 * ty + 16 * p;
        ull bp = pack2(b1[c], b1[c + 1]);
        #pragma unroll
        for (int j = 0; j < 8; j++) acc[p][j] = bp;
    }
    #pragma unroll 2
    for (int cin = 0; cin < CTOT; cin++) {
        const float* wrow = &Ws[cin * 64 + 2 * ty];
        ull w0 = *(const ull*)(wrow);
        ull w1v = *(const ull*)(wrow + 16);
        ull w2v = *(const ull*)(wrow + 32);
        ull w3v = *(const ull*)(wrow + 48);
        const float4* xq = (const float4*)&Xs[cin * 136 + sbase];
        float4 xa = xq[0], xb = xq[1];
        ull xd[8];
        xd[0] = pack2(xa.x, xa.x); xd[1] = pack2(xa.y, xa.y);
        xd[2] = pack2(xa.z, xa.z); xd[3] = pack2(xa.w, xa.w);
        xd[4] = pack2(xb.x, xb.x); xd[5] = pack2(xb.y, xb.y);
        xd[6] = pack2(xb.z, xb.z); xd[7] = pack2(xb.w, xb.w);
        #pragma unroll
        for (int j = 0; j < 8; j++) {
            acc[0][j] = fma2(w0,  xd[j], acc[0][j]);
            acc[1][j] = fma2(w1v, xd[j], acc[1][j]);
            acc[2][j] = fma2(w2v, xd[j], acc[2][j]);
            acc[3][j] = fma2(w3v, xd[j], acc[3][j]);
        }
    }

    // store outputs + packed stats partials
    #pragma unroll
    for (int p = 0; p < 4; p++) {
        const int cl = 2 * ty + 16 * p, ch = cl + 1;
        float lo[8], hi[8];
        #pragma unroll
        for (int j = 0; j < 8; j++) unpack2(acc[p][j], lo[j], hi[j]);
        size_t bl_ = ((size_t)b * HID + cl) * SPAT + s0 + sbase;
        size_t bh_ = ((size_t)b * HID + ch) * SPAT + s0 + sbase;
        *(float4*)&g_x1[bl_]     = make_float4(lo[0], lo[1], lo[2], lo[3]);
        *(float4*)&g_x1[bl_ + 4] = make_float4(lo[4], lo[5], lo[6], lo[7]);
        *(float4*)&g_x1[bh_]     = make_float4(hi[0], hi[1], hi[2], hi[3]);
        *(float4*)&g_x1[bh_ + 4] = make_float4(hi[4], hi[5], hi[6], hi[7]);
    }
    // packed sums over this thread's 8 spatial positions
    ull ssum[4], ssq[4];
    #pragma unroll
    for (int p = 0; p < 4; p++) {
        ull s = add2(add2(acc[p][0], acc[p][1]), add2(acc[p][2], acc[p][3]));
        s = add2(s, add2(add2(acc[p][4], acc[p][5]), add2(acc[p][6], acc[p][7])));
        ull q = mul2(acc[p][0], acc[p][0]);
        #pragma unroll
        for (int j = 1; j < 8; j++) q = fma2(acc[p][j], acc[p][j], q);
        ssum[p] = s; ssq[p] = q;
    }
    #pragma unroll
    for (int p = 0; p < 4; p++) {
        ssum[p] = add2(ssum[p], __shfl_down_sync(FULLMASK, ssum[p], 8));
        ssum[p] = add2(ssum[p], __shfl_down_sync(FULLMASK, ssum[p], 16));
        ssq[p]  = add2(ssq[p],  __shfl_down_sync(FULLMASK, ssq[p],  8));
        ssq[p]  = add2(ssq[p],  __shfl_down_sync(FULLMASK, ssq[p],  16));
    }
    if (lane < 8) {
        #pragma unroll
        for (int p = 0; p < 4; p++) {
            spart_s[warp][lane * 4 + p] = ssum[p];
            spart_q[warp][lane * 4 + p] = ssq[p];
        }
    }
    __syncthreads();
    if (tid < 32) {
        int i = tid, typ = i >> 2, pp = i & 3;
        int cl = 2 * typ + 16 * pp;
        ull s = add2(add2(spart_s[0][i], spart_s[1][i]),
                     add2(spart_s[2][i], spart_s[3][i]));
        ull q = add2(add2(spart_q[0][i], spart_q[1][i]),
                     add2(spart_q[2][i], spart_q[3][i]));
        float sl, sh, ql, qh;
        unpack2(s, sl, sh); unpack2(q, ql, qh);
        int pi0 = ((b * HID + cl) * NB1 + bx) * 2;
        int pi1 = ((b * HID + cl + 1) * NB1 + bx) * 2;
        g_p1[pi0] = sl; g_p1[pi0 + 1] = ql;
        g_p1[pi1] = sh; g_p1[pi1 + 1] = qh;
    }
}

// ---------------- K4/K6: reduce stats partials ----------------
__global__ void __launch_bounds__(256)
stats1_kernel() {
    const int bid = blockIdx.x;                    // b*HID + c
    float s = 0.f, q = 0.f;
    for (int i = threadIdx.x; i < NB1; i += 256) {
        s += g_p1[(bid * NB1 + i) * 2];
        q += g_p1[(bid * NB1 + i) * 2 + 1];
    }
    float2 r = blk_reduce2(s, q);
    if (threadIdx.x == 0) { g_cs1[bid * 2] = r.x; g_cs1[bid * 2 + 1] = r.y; }
}

__global__ void __launch_bounds__(256)
stats2_kernel() {
    const int bid = blockIdx.x;                    // b*OUTC + c
    float s = 0.f, q = 0.f;
    for (int i = threadIdx.x; i < NBLK; i += 256) {
        s += g_p2[(bid * NBLK + i) * 2];
        q += g_p2[(bid * NBLK + i) * 2 + 1];
    }
    float2 r = blk_reduce2(s, q);
    if (threadIdx.x == 0) { g_cs2[bid * 2] = r.x; g_cs2[bid * 2 + 1] = r.y; }
}

// ---------------- K5: GN1+ReLU + conv2 (8x8 reg-blocked FFMA2) --------------
// 128 threads; block tile 128 cout x 64 spat. ty=tid&15, tx=tid>>4.
// Thread couts: {2ty+32p, +1} p=0..3; spat [tx*8, tx*8+8) (single m per thread).
__global__ void __launch_bounds__(128)
conv2_kernel(const float* __restrict__ w2, const float* __restrict__ b2,
             const float* __restrict__ g1w, const float* __restrict__ g1b) {
    extern __shared__ float dsm[];
    float* Ws = dsm;                           // [cin][128] 32 KB
    float* Hs = dsm + HID * OUTC;              // [cin][72]  18 KB
    float* sc = Hs + HID * 72;                 // 64
    float* sh = sc + HID;                      // 64
    __shared__ float4 pmm[4][64];              // (mx_lo, mx_hi, mn_lo, mn_hi)
    __shared__ ull   psum[4][64];
    __shared__ ull   psq[4][64];
    const int b = blockIdx.y, bx = blockIdx.x, s0 = bx * 64, tid = threadIdx.x;
    const int warp = tid >> 5, lane = tid & 31;

    for (int i = tid; i < HID * OUTC; i += 128) {
        int cin = i >> 7, c = i & 127;
        Ws[i] = w2[c * HID + cin];
    }
    if (tid < HID) {
        int c = tid, g = c >> 1, cb = b * HID + g * 2;
        float sum = g_cs1[cb * 2]     + g_cs1[(cb + 1) * 2];
        float sq  = g_cs1[cb * 2 + 1] + g_cs1[(cb + 1) * 2 + 1];
        float inv = 1.0f / 65536.0f;
        float mu = sum * inv;
        float var = sq * inv - mu * mu;
        float a = rsqrtf(var + EPSV) * g1w[c];
        sc[c] = a;
        sh[c] = g1b[c] - mu * a;
    }
    __syncthreads();
    {
        const int c = tid >> 1, seg = (tid & 1) * 32;
        const float* p = g_x1 + ((size_t)b * HID + c) * SPAT + s0 + seg;
        float a = sc[c], o = sh[c];
        #pragma unroll
        for (int q = 0; q < 8; q++) {
            float4 v = *(const float4*)(p + q * 4);
            Hs[c * 72 + seg + q * 4 + 0] = fmaxf(fmaf(v.x, a, o), 0.f);
            Hs[c * 72 + seg + q * 4 + 1] = fmaxf(fmaf(v.y, a, o), 0.f);
            Hs[c * 72 + seg + q * 4 + 2] = fmaxf(fmaf(v.z, a, o), 0.f);
            Hs[c * 72 + seg + q * 4 + 3] = fmaxf(fmaf(v.w, a, o), 0.f);
        }
    }
    __syncthreads();

    const int ty = tid & 15, tx = tid >> 4, sbase = tx * 8;
    ull acc[4][8];
    #pragma unroll
    for (int p = 0; p < 4; p++) {
        int c = 2 * ty + 32 * p;
        ull bp = pack2(b2[c], b2[c + 1]);
        #pragma unroll
        for (int j = 0; j < 8; j++) acc[p][j] = bp;
    }
    #pragma unroll 2
    for (int cin = 0; cin < HID; cin++) {
        const float* wrow = &Ws[cin * OUTC + 2 * ty];
        ull w0 = *(const ull*)(wrow);
        ull w1v = *(const ull*)(wrow + 32);
        ull w2v = *(const ull*)(wrow + 64);
        ull w3v = *(const ull*)(wrow + 96);
        const float4* xq = (const float4*)&Hs[cin * 72 + sbase];
        float4 xa = xq[0], xb = xq[1];
        ull xd[8];
        xd[0] = pack2(xa.x, xa.x); xd[1] = pack2(xa.y, xa.y);
        xd[2] = pack2(xa.z, xa.z); xd[3] = pack2(xa.w, xa.w);
        xd[4] = pack2(xb.x, xb.x); xd[5] = pack2(xb.y, xb.y);
        xd[6] = pack2(xb.z, xb.z); xd[7] = pack2(xb.w, xb.w);
        #pragma unroll
        for (int j = 0; j < 8; j++) {
            acc[0][j] = fma2(w0,  xd[j], acc[0][j]);
            acc[1][j] = fma2(w1v, xd[j], acc[1][j]);
            acc[2][j] = fma2(w2v, xd[j], acc[2][j]);
            acc[3][j] = fma2(w3v, xd[j], acc[3][j]);
        }
    }

    // epilogue: per-pair max/min over this thread's 8 k-positions + packed stats
    #pragma unroll
    for (int p = 0; p < 4; p++) {
        float lo[8], hi[8];
        #pragma unroll
        for (int j = 0; j < 8; j++) unpack2(acc[p][j], lo[j], hi[j]);
        float mxl = lo[0], mnl = lo[0], mxh = hi[0], mnh = hi[0];
        #pragma unroll
        for (int j = 1; j < 8; j++) {
            mxl = fmaxf(mxl, lo[j]); mnl = fminf(mnl, lo[j]);
            mxh = fmaxf(mxh, hi[j]); mnh = fminf(mnh, hi[j]);
        }
        // merge the two tx values in this warp (lanes +-16): same m-half
        mxl = fmaxf(mxl, __shfl_down_sync(FULLMASK, mxl, 16));
        mnl = fminf(mnl, __shfl_down_sync(FULLMASK, mnl, 16));
        mxh = fmaxf(mxh, __shfl_down_sync(FULLMASK, mxh, 16));
        mnh = fminf(mnh, __shfl_down_sync(FULLMASK, mnh, 16));
        ull s = add2(add2(acc[p][0], acc[p][1]), add2(acc[p][2], acc[p][3]));
        s = add2(s, add2(add2(acc[p][4], acc[p][5]), add2(acc[p][6], acc[p][7])));
        ull q = mul2(acc[p][0], acc[p][0]);
        #pragma unroll
        for (int j = 1; j < 8; j++) q = fma2(acc[p][j], acc[p][j], q);
        s = add2(s, __shfl_down_sync(FULLMASK, s, 16));
        q = add2(q, __shfl_down_sync(FULLMASK, q, 16));
        if (lane < 16) {
            pmm[warp][lane * 4 + p] = make_float4(mxl, mxh, mnl, mnh);
            psum[warp][lane * 4 + p] = s;
            psq[warp][lane * 4 + p] = q;
        }
    }
    __syncthreads();
    if (tid < 64) {
        const int i = tid, typ = i >> 2, pp = i & 3;
        const int cl = 2 * typ + 32 * pp, ch = cl + 1;
        const int m0i = s0 >> 5, m1i = m0i + 1;
        float4 a0 = pmm[0][i], a1 = pmm[1][i], a2 = pmm[2][i], a3 = pmm[3][i];
        // m0: warps 0,1 (spat 0..31); m1: warps 2,3
        size_t o0 = ((size_t)b * M_ + m0i) * OUTC;
        size_t o1 = ((size_t)b * M_ + m1i) * OUTC;
        g_mx2[o0 + cl] = fmaxf(a0.x, a1.x);  g_mx2[o0 + ch] = fmaxf(a0.y, a1.y);
        g_mn2[o0 + cl] = fminf(a0.z, a1.z);  g_mn2[o0 + ch] = fminf(a0.w, a1.w);
        g_mx2[o1 + cl] = fmaxf(a2.x, a3.x);  g_mx2[o1 + ch] = fmaxf(a2.y, a3.y);
        g_mn2[o1 + cl] = fminf(a2.z, a3.z);  g_mn2[o1 + ch] = fminf(a2.w, a3.w);
        ull s = add2(add2(psum[0][i], psum[1][i]), add2(psum[2][i], psum[3][i]));
        ull q = add2(add2(psq[0][i],  psq[1][i]),  add2(psq[2][i],  psq[3][i]));
        float sl, shv, ql, qh;
        unpack2(s, sl, shv); unpack2(q, ql, qh);
        int pi0 = ((b * OUTC + cl) * NBLK + bx) * 2;
        int pi1 = ((b * OUTC + ch) * NBLK + bx) * 2;
        g_p2[pi0] = sl; g_p2[pi0 + 1] = ql;
        g_p2[pi1] = shv; g_p2[pi1 + 1] = qh;
    }
}

// ---------------- K7: GN2 affine on max/min (monotone -> exact) ----------------
__global__ void __launch_bounds__(256)
final_kernel(const float* __restrict__ g2w, const float* __restrict__ g2b,
             float* __restrict__ out) {
    const int b = blockIdx.y;
    const int tid = threadIdx.x;
    const int c = tid & 127;
    const int m = blockIdx.x * 2 + (tid >> 7);
    const int g = c >> 2, cb = b * OUTC + g * 4;
    float sum = 0.f, sq = 0.f;
    #pragma unroll
    for (int q = 0; q < 4; q++) {
        sum += g_cs2[(cb + q) * 2];
        sq  += g_cs2[(cb + q) * 2 + 1];
    }
    const float inv = 1.0f / 131072.0f;
    float mu = sum * inv;
    float var = sq * inv - mu * mu;
    float a = rsqrtf(var + EPSV) * g2w[c];
    float o = g2b[c] - mu * a;
    size_t off = ((size_t)b * M_ + m) * OUTC + c;
    float mx = g_mx2[off], mn = g_mn2[off];
    float v = (a >= 0.f) ? fmaf(mx, a, o) : fmaf(mn, a, o);
    out[off] = fmaxf(v, 0.f);
}

// ---------------- launch ----------------
extern "C" void kernel_launch(void* const* d_in, const int* in_sizes, int n_in,
                              void* d_out, int out_size) {
    const float* xyz  = (const float*)d_in[0];
    const float* feat = (const float*)d_in[1];
    const float* w1   = (const float*)d_in[2];
    const float* b1   = (const float*)d_in[3];
    const float* g1w  = (const float*)d_in[4];
    const float* g1b  = (const float*)d_in[5];
    const float* w2   = (const float*)d_in[6];
    const float* b2   = (const float*)d_in[7];
    const float* g2w  = (const float*)d_in[8];
    const float* g2b  = (const float*)d_in[9];

    float* out = (float*)d_out;
    float* cent;
    float* nf;
    if (out_size == B_ * M_ * 3 + B_ * M_ * OUTC) {
        cent = out;
        nf = out + (size_t)B_ * M_ * 3;
    } else {
        void* p = nullptr;
        cudaGetSymbolAddress(&p, g_centfb);
        cent = (float*)p;
        nf = out;
    }

    const int c1smem = (CTOT * 64 + CTOT * 136) * 4;
    const int c2smem = (HID * OUTC + HID * 72 + 2 * HID) * 4;
    cudaFuncSetAttribute(fps_kernel,  cudaFuncAttributeMaxDynamicSharedMemorySize, 3 * N_ * 4);
    cudaFuncSetAttribute(knn_kernel,  cudaFuncAttributeMaxDynamicSharedMemorySize, 4 * N_ * 4);
    cudaFuncSetAttribute(conv1_kernel, cudaFuncAttributeMaxDynamicSharedMemorySize, c1smem);
    cudaFuncSetAttribute(conv2_kernel, cudaFuncAttributeMaxDynamicSharedMemorySize, c2smem);

    // 3 dummies shift the ncu capture slot (historically launch #4) onto fps
    dummy_kernel<<<1, 32>>>(1);
    dummy_kernel<<<1, 32>>>(2);
    dummy_kernel<<<1, 32>>>(3);
    fps_kernel<<<B_, 512, 3 * N_ * 4>>>(xyz, cent);
    knn_kernel<<<dim3(B_, 16), 256, 4 * N_ * 4>>>(xyz, cent);
    conv1_kernel<<<dim3(NB1, B_), 128, c1smem>>>(xyz, feat, w1, b1, cent);
    stats1_kernel<<<B_ * HID, 256>>>();
    conv2_kernel<<<dim3(NBLK, B_), 128, c2smem>>>(w2, b2, g1w, g1b);
    stats2_kernel<<<B_ * OUTC, 256>>>();
    final_kernel<<<dim3(M_ / 2, B_), 256>>>(g2w, g2b, nf);
}